// round 7
// baseline (speedup 1.0000x reference)
#include <cuda_runtime.h>
#include <math.h>

#define WG 640      // grid "w" dimension (output dim 2)
#define HG 480      // grid "h" dimension (output dim 3, innermost)
#define IMW 640     // image width
#define IMH 480     // image height
#define MAXB 64
#define HQ (HG / 4)          // float4 groups along h (120)
#define QPB (WG * HQ)        // float4 groups per batch (76800)
#define NPB1 38              // pass1 blocks per batch
#define THREADS 256

__device__ float g_part[NPB1 * MAXB];   // per-block partial maxima (all overwritten each launch)

// ---------------------------------------------------------------------------
// Per-batch fold: M = K^-1 @ T[0:3,0:3] @ K (row-vector), C = T[3,0:3] @ K.
// ---------------------------------------------------------------------------
__device__ __forceinline__ void compute_fold(const float* __restrict__ T,
                                             const float* __restrict__ K,
                                             int b, float* sM, float* sC) {
    float a = K[0], bb = K[1], c = K[2];
    float d = K[3], e = K[4], f = K[5];
    float g = K[6], h = K[7], i = K[8];
    float det = a * (e * i - f * h) - bb * (d * i - f * g) + c * (d * h - e * g);
    float inv = 1.0f / det;
    float Ki[9];
    Ki[0] = (e * i - f * h) * inv; Ki[1] = (c * h - bb * i) * inv; Ki[2] = (bb * f - c * e) * inv;
    Ki[3] = (f * g - d * i) * inv; Ki[4] = (a * i - c * g) * inv;  Ki[5] = (c * d - a * f) * inv;
    Ki[6] = (d * h - e * g) * inv; Ki[7] = (bb * g - a * h) * inv; Ki[8] = (a * e - bb * d) * inv;

    const float* Tb = T + b * 16;
    float A[9];
    #pragma unroll
    for (int r = 0; r < 3; r++)
        #pragma unroll
        for (int cc = 0; cc < 3; cc++)
            A[r * 3 + cc] = Ki[r * 3 + 0] * Tb[0 * 4 + cc]
                          + Ki[r * 3 + 1] * Tb[1 * 4 + cc]
                          + Ki[r * 3 + 2] * Tb[2 * 4 + cc];
    #pragma unroll
    for (int r = 0; r < 3; r++)
        #pragma unroll
        for (int cc = 0; cc < 3; cc++)
            sM[r * 3 + cc] = A[r * 3 + 0] * K[0 * 3 + cc]
                           + A[r * 3 + 1] * K[1 * 3 + cc]
                           + A[r * 3 + 2] * K[2 * 3 + cc];
    #pragma unroll
    for (int cc = 0; cc < 3; cc++)
        sC[cc] = Tb[12] * K[cc] + Tb[13] * K[3 + cc] + Tb[14] * K[6 + cc];
}

// ---------------------------------------------------------------------------
// Pass 1: per-block max over uv components -> g_part (no reset needed)
// ---------------------------------------------------------------------------
__global__ void stn_max(const float4* __restrict__ depth4,
                        const float* __restrict__ T,
                        const float* __restrict__ K) {
    __shared__ float sM[9], sC[3];
    int b = blockIdx.y;
    if (threadIdx.x == 0) compute_fold(T, K, b, sM, sC);
    __syncthreads();

    const float4* dep4 = depth4 + (size_t)b * QPB;
    float m = -INFINITY;
    for (int q = blockIdx.x * THREADS + threadIdx.x; q < QPB; q += NPB1 * THREADS) {
        int hq = q % HQ;
        int w  = q / HQ;
        float fh = (float)(hq * 4), fw = (float)w;
        float t0 = fh * sM[0] + fw * sM[3] + sM[6];
        float t1 = fh * sM[1] + fw * sM[4] + sM[7];
        float t2 = fh * sM[2] + fw * sM[5] + sM[8];
        float4 d4 = dep4[q];
        float dep[4] = {d4.x, d4.y, d4.z, d4.w};
        #pragma unroll
        for (int i = 0; i < 4; i++) {
            float d0 = dep[i] * t0 + sC[0];
            float d1 = dep[i] * t1 + sC[1];
            float d2 = dep[i] * t2 + sC[2];
            float r = __fdividef(1.0f, d2 + 1e-4f);
            m = fmaxf(m, fmaxf(d0 * r, d1 * r));
            t0 += sM[0]; t1 += sM[1]; t2 += sM[2];
        }
    }
    #pragma unroll
    for (int off = 16; off > 0; off >>= 1)
        m = fmaxf(m, __shfl_xor_sync(0xFFFFFFFF, m, off));
    __shared__ float sm[THREADS / 32];
    int lane = threadIdx.x & 31, wid = threadIdx.x >> 5;
    if (lane == 0) sm[wid] = m;
    __syncthreads();
    if (wid == 0) {
        m = (lane < THREADS / 32) ? sm[lane] : -INFINITY;
        #pragma unroll
        for (int off = 16; off > 0; off >>= 1)
            m = fmaxf(m, __shfl_xor_sync(0xFFFFFFFF, m, off));
        if (lane == 0) g_part[b * NPB1 + blockIdx.x] = m;
    }
}

// ---------------------------------------------------------------------------
// Pass 2: lane-consecutive-h mapping. Block = 8 warps; warps 0-3 -> w0,
// warps 4-7 -> w1. Warp q covers h in [128q, 128q+128); thread pixel i is
// h = 128q + lane + 32i. Gather wavefronts see consecutive image columns.
// Branchy bilinear body (fastest variant, R3).
// ---------------------------------------------------------------------------
__global__ void stn_sample(const float* __restrict__ depth,
                           const float* __restrict__ image,
                           const float* __restrict__ T,
                           const float* __restrict__ K,
                           float* __restrict__ out, int npart) {
    __shared__ float sM[9], sC[3];
    __shared__ float swm[THREADS / 32];
    int b = blockIdx.y;
    int tid = threadIdx.x;
    int lane = tid & 31, wrp = tid >> 5;

    // reduce global partial maxima (hot in L2): per-warp shuffle, one sync
    float m = -INFINITY;
    for (int i = tid; i < npart; i += THREADS) m = fmaxf(m, g_part[i]);
    #pragma unroll
    for (int off = 16; off > 0; off >>= 1)
        m = fmaxf(m, __shfl_xor_sync(0xFFFFFFFF, m, off));
    if (lane == 0) swm[wrp] = m;
    if (tid == 0) compute_fold(T, K, b, sM, sC);
    __syncthreads();
    float Mx = fmaxf(fmaxf(fmaxf(swm[0], swm[1]), fmaxf(swm[2], swm[3])),
                     fmaxf(fmaxf(swm[4], swm[5]), fmaxf(swm[6], swm[7])));

    float cw = __fdividef((float)IMW, Mx);
    float ch = __fdividef((float)IMH, Mx);

    int w  = blockIdx.x * 2 + (wrp >> 2);   // w column for this warp
    int hb = (wrp & 3) * 128;               // h base for this warp

    float fw = (float)w;
    float fh0 = (float)(hb + lane);
    float t0 = fh0 * sM[0] + fw * sM[3] + sM[6];
    float t1 = fh0 * sM[1] + fw * sM[4] + sM[7];
    float t2 = fh0 * sM[2] + fw * sM[5] + sM[8];
    float m32_0 = 32.0f * sM[0], m32_1 = 32.0f * sM[1], m32_2 = 32.0f * sM[2];

    const float* dep_row = depth + ((size_t)b * WG + w) * HG;
    const float* img = image + (size_t)b * 3 * IMH * IMW;
    const int chs = IMH * IMW;
    float* out_row = out + ((size_t)(b * 3) * WG + w) * HG;
    const size_t ostride = (size_t)WG * HG;

    #pragma unroll
    for (int i = 0; i < 4; i++) {
        int h = hb + lane + 32 * i;
        if (h >= HG) break;                 // warp-uniform (only warp q=3, i=3)

        float dv = dep_row[h];              // coalesced scalar load
        float d0 = dv * t0 + sC[0];
        float d1 = dv * t1 + sC[1];
        float d2 = dv * t2 + sC[2];
        t0 += m32_0; t1 += m32_1; t2 += m32_2;
        float r = __fdividef(1.0f, d2 + 1e-4f);
        float x = d0 * r * cw - 0.5f;
        float y = d1 * r * ch - 0.5f;

        float x0f = floorf(x), y0f = floorf(y);
        float wx = x - x0f, wy = y - y0f;
        int x0 = (int)x0f, y0 = (int)y0f;
        int x1 = x0 + 1, y1 = y0 + 1;

        float w00 = (1.0f - wx) * (1.0f - wy);
        float w01 = wx * (1.0f - wy);
        float w10 = (1.0f - wx) * wy;
        float w11 = wx * wy;

        bool vx0 = (x0 >= 0) && (x0 < IMW);
        bool vx1 = (x1 >= 0) && (x1 < IMW);
        bool vy0 = (y0 >= 0) && (y0 < IMH);
        bool vy1 = (y1 >= 0) && (y1 < IMH);

        float s0 = 0.0f, s1 = 0.0f, s2 = 0.0f;
        if (vy0) {
            int row = y0 * IMW;
            if (vx0) {
                int o = row + x0;
                s0 += w00 * img[o]; s1 += w00 * img[chs + o]; s2 += w00 * img[2 * chs + o];
            }
            if (vx1) {
                int o = row + x1;
                s0 += w01 * img[o]; s1 += w01 * img[chs + o]; s2 += w01 * img[2 * chs + o];
            }
        }
        if (vy1) {
            int row = y1 * IMW;
            if (vx0) {
                int o = row + x0;
                s0 += w10 * img[o]; s1 += w10 * img[chs + o]; s2 += w10 * img[2 * chs + o];
            }
            if (vx1) {
                int o = row + x1;
                s0 += w11 * img[o]; s1 += w11 * img[chs + o]; s2 += w11 * img[2 * chs + o];
            }
        }

        // coalesced scalar stores (lane-consecutive h)
        out_row[h]               = s0;
        out_row[h + ostride]     = s1;
        out_row[h + 2 * ostride] = s2;
    }
}

extern "C" void kernel_launch(void* const* d_in, const int* in_sizes, int n_in,
                              void* d_out, int out_size) {
    const float* depth = (const float*)d_in[0];   // [B, 640, 480, 1]
    const float* trans = (const float*)d_in[1];   // [B, 4, 4]
    const float* image = (const float*)d_in[2];   // [B, 3, 480, 640]
    const float* K     = (const float*)d_in[3];   // [3, 3]
    float* out = (float*)d_out;                   // [B, 3, 640, 480]

    int B = in_sizes[0] / (WG * HG);

    dim3 g1(NPB1, B);
    stn_max<<<g1, THREADS>>>((const float4*)depth, trans, K);

    dim3 g2(WG / 2, B);   // 320 x B blocks, 8 warps each (2 w-columns/block)
    stn_sample<<<g2, THREADS>>>(depth, image, trans, K, out, NPB1 * B);
}

// round 10
// speedup vs baseline: 1.2397x; 1.2397x over previous
#include <cuda_runtime.h>
#include <math.h>

#define WG 640      // grid "w" dimension (output dim 2)
#define HG 480      // grid "h" dimension (output dim 3, innermost)
#define IMW 640     // image width
#define IMH 480     // image height
#define MAXB 64
#define HQ (HG / 4)          // float4 groups along h (120)
#define QPB (WG * HQ)        // float4 groups per batch (76800)
#define NPB1 38              // pass1 blocks per batch
#define THREADS 256

__device__ float g_part[NPB1 * MAXB];     // per-block partials (all overwritten each launch)
__device__ unsigned int g_ctr = 0;        // wrapping counter: returns to 0 every launch
__device__ float g_final;                 // overwritten by pass1's last block each launch

// ---------------------------------------------------------------------------
// Per-batch fold: M = K^-1 @ T[0:3,0:3] @ K (row-vector), C = T[3,0:3] @ K.
// ---------------------------------------------------------------------------
__device__ __forceinline__ void compute_fold(const float* __restrict__ T,
                                             const float* __restrict__ K,
                                             int b, float* sM, float* sC) {
    float a = K[0], bb = K[1], c = K[2];
    float d = K[3], e = K[4], f = K[5];
    float g = K[6], h = K[7], i = K[8];
    float det = a * (e * i - f * h) - bb * (d * i - f * g) + c * (d * h - e * g);
    float inv = 1.0f / det;
    float Ki[9];
    Ki[0] = (e * i - f * h) * inv; Ki[1] = (c * h - bb * i) * inv; Ki[2] = (bb * f - c * e) * inv;
    Ki[3] = (f * g - d * i) * inv; Ki[4] = (a * i - c * g) * inv;  Ki[5] = (c * d - a * f) * inv;
    Ki[6] = (d * h - e * g) * inv; Ki[7] = (bb * g - a * h) * inv; Ki[8] = (a * e - bb * d) * inv;

    const float* Tb = T + b * 16;
    float A[9];
    #pragma unroll
    for (int r = 0; r < 3; r++)
        #pragma unroll
        for (int cc = 0; cc < 3; cc++)
            A[r * 3 + cc] = Ki[r * 3 + 0] * Tb[0 * 4 + cc]
                          + Ki[r * 3 + 1] * Tb[1 * 4 + cc]
                          + Ki[r * 3 + 2] * Tb[2 * 4 + cc];
    #pragma unroll
    for (int r = 0; r < 3; r++)
        #pragma unroll
        for (int cc = 0; cc < 3; cc++)
            sM[r * 3 + cc] = A[r * 3 + 0] * K[0 * 3 + cc]
                           + A[r * 3 + 1] * K[1 * 3 + cc]
                           + A[r * 3 + 2] * K[2 * 3 + cc];
    #pragma unroll
    for (int cc = 0; cc < 3; cc++)
        sC[cc] = Tb[12] * K[cc] + Tb[13] * K[3 + cc] + Tb[14] * K[6 + cc];
}

// ---------------------------------------------------------------------------
// Pass 1: per-block max -> g_part; last block reduces partials -> g_final.
// ---------------------------------------------------------------------------
__global__ void stn_max(const float4* __restrict__ depth4,
                        const float* __restrict__ T,
                        const float* __restrict__ K, int npart) {
    __shared__ float sM[9], sC[3];
    int b = blockIdx.y;
    if (threadIdx.x == 0) compute_fold(T, K, b, sM, sC);
    __syncthreads();

    const float4* dep4 = depth4 + (size_t)b * QPB;
    float m = -INFINITY;
    for (int q = blockIdx.x * THREADS + threadIdx.x; q < QPB; q += NPB1 * THREADS) {
        int hq = q % HQ;
        int w  = q / HQ;
        float fh = (float)(hq * 4), fw = (float)w;
        float t0 = fh * sM[0] + fw * sM[3] + sM[6];
        float t1 = fh * sM[1] + fw * sM[4] + sM[7];
        float t2 = fh * sM[2] + fw * sM[5] + sM[8];
        float4 d4 = dep4[q];
        float dep[4] = {d4.x, d4.y, d4.z, d4.w};
        #pragma unroll
        for (int i = 0; i < 4; i++) {
            float d0 = dep[i] * t0 + sC[0];
            float d1 = dep[i] * t1 + sC[1];
            float d2 = dep[i] * t2 + sC[2];
            float r = __fdividef(1.0f, d2 + 1e-4f);
            m = fmaxf(m, fmaxf(d0 * r, d1 * r));
            t0 += sM[0]; t1 += sM[1]; t2 += sM[2];
        }
    }
    // block reduce
    #pragma unroll
    for (int off = 16; off > 0; off >>= 1)
        m = fmaxf(m, __shfl_xor_sync(0xFFFFFFFF, m, off));
    __shared__ float sm[THREADS / 32];
    __shared__ bool is_last;
    int lane = threadIdx.x & 31, wid = threadIdx.x >> 5;
    if (lane == 0) sm[wid] = m;
    __syncthreads();
    if (threadIdx.x == 0) {
        float bm = sm[0];
        #pragma unroll
        for (int i = 1; i < THREADS / 32; i++) bm = fmaxf(bm, sm[i]);
        g_part[b * NPB1 + blockIdx.x] = bm;
        __threadfence();
        // wrapping counter: after exactly npart increments it is 0 again,
        // so the launch is replay-deterministic with no reset kernel.
        unsigned int old = atomicInc(&g_ctr, (unsigned int)(npart - 1));
        is_last = (old == (unsigned int)(npart - 1));
    }
    __syncthreads();
    if (is_last) {
        float mm = -INFINITY;
        for (int i = threadIdx.x; i < npart; i += THREADS) mm = fmaxf(mm, g_part[i]);
        #pragma unroll
        for (int off = 16; off > 0; off >>= 1)
            mm = fmaxf(mm, __shfl_xor_sync(0xFFFFFFFF, mm, off));
        if (lane == 0) sm[wid] = mm;
        __syncthreads();
        if (threadIdx.x == 0) {
            float bm = sm[0];
            #pragma unroll
            for (int i = 1; i < THREADS / 32; i++) bm = fmaxf(bm, sm[i]);
            g_final = bm;
        }
    }
}

// ---------------------------------------------------------------------------
// Pass 2: R3's proven body — float4 over h, branchy bilinear, plain stores.
// ---------------------------------------------------------------------------
__global__ void stn_sample(const float4* __restrict__ depth4,
                           const float* __restrict__ image,
                           const float* __restrict__ T,
                           const float* __restrict__ K,
                           float4* __restrict__ out4) {
    __shared__ float sM[9], sC[3];
    int b = blockIdx.y;
    if (threadIdx.x == 0) compute_fold(T, K, b, sM, sC);
    __syncthreads();

    float Mx = g_final;                     // single L2-hit load
    float cw = __fdividef((float)IMW, Mx);
    float ch = __fdividef((float)IMH, Mx);

    int q = blockIdx.x * THREADS + threadIdx.x;
    if (q >= QPB) return;
    int hq = q % HQ;
    int w  = q / HQ;

    float fh = (float)(hq * 4), fw = (float)w;
    float t0 = fh * sM[0] + fw * sM[3] + sM[6];
    float t1 = fh * sM[1] + fw * sM[4] + sM[7];
    float t2 = fh * sM[2] + fw * sM[5] + sM[8];

    float4 d4 = depth4[(size_t)b * QPB + q];
    float dep[4] = {d4.x, d4.y, d4.z, d4.w};

    const float* img = image + (size_t)b * 3 * IMH * IMW;
    const int chs = IMH * IMW;

    float a0[4], a1[4], a2[4];

    #pragma unroll
    for (int i = 0; i < 4; i++) {
        float d0 = dep[i] * t0 + sC[0];
        float d1 = dep[i] * t1 + sC[1];
        float d2 = dep[i] * t2 + sC[2];
        t0 += sM[0]; t1 += sM[1]; t2 += sM[2];
        float r = __fdividef(1.0f, d2 + 1e-4f);
        float x = d0 * r * cw - 0.5f;
        float y = d1 * r * ch - 0.5f;

        float x0f = floorf(x), y0f = floorf(y);
        float wx = x - x0f, wy = y - y0f;
        int x0 = (int)x0f, y0 = (int)y0f;
        int x1 = x0 + 1, y1 = y0 + 1;

        float w00 = (1.0f - wx) * (1.0f - wy);
        float w01 = wx * (1.0f - wy);
        float w10 = (1.0f - wx) * wy;
        float w11 = wx * wy;

        bool vx0 = (x0 >= 0) && (x0 < IMW);
        bool vx1 = (x1 >= 0) && (x1 < IMW);
        bool vy0 = (y0 >= 0) && (y0 < IMH);
        bool vy1 = (y1 >= 0) && (y1 < IMH);

        float s0 = 0.0f, s1 = 0.0f, s2 = 0.0f;
        if (vy0) {
            int row = y0 * IMW;
            if (vx0) {
                int o = row + x0;
                s0 += w00 * img[o]; s1 += w00 * img[chs + o]; s2 += w00 * img[2 * chs + o];
            }
            if (vx1) {
                int o = row + x1;
                s0 += w01 * img[o]; s1 += w01 * img[chs + o]; s2 += w01 * img[2 * chs + o];
            }
        }
        if (vy1) {
            int row = y1 * IMW;
            if (vx0) {
                int o = row + x0;
                s0 += w10 * img[o]; s1 += w10 * img[chs + o]; s2 += w10 * img[2 * chs + o];
            }
            if (vx1) {
                int o = row + x1;
                s0 += w11 * img[o]; s1 += w11 * img[chs + o]; s2 += w11 * img[2 * chs + o];
            }
        }
        a0[i] = s0; a1[i] = s1; a2[i] = s2;
    }

    // out[b, c, w, h], h innermost; float4 groups along h (write-back stores)
    size_t base = ((size_t)(b * 3) * WG + w) * HQ + hq;  // float4 units
    const size_t ostride = (size_t)WG * HQ;
    out4[base]               = make_float4(a0[0], a0[1], a0[2], a0[3]);
    out4[base + ostride]     = make_float4(a1[0], a1[1], a1[2], a1[3]);
    out4[base + 2 * ostride] = make_float4(a2[0], a2[1], a2[2], a2[3]);
}

extern "C" void kernel_launch(void* const* d_in, const int* in_sizes, int n_in,
                              void* d_out, int out_size) {
    const float* depth = (const float*)d_in[0];   // [B, 640, 480, 1]
    const float* trans = (const float*)d_in[1];   // [B, 4, 4]
    const float* image = (const float*)d_in[2];   // [B, 3, 480, 640]
    const float* K     = (const float*)d_in[3];   // [3, 3]
    float* out = (float*)d_out;                   // [B, 3, 640, 480]

    int B = in_sizes[0] / (WG * HG);
    int npart = NPB1 * B;

    dim3 g1(NPB1, B);
    stn_max<<<g1, THREADS>>>((const float4*)depth, trans, K, npart);

    dim3 g2((QPB + THREADS - 1) / THREADS, B);   // 300 x B
    stn_sample<<<g2, THREADS>>>((const float4*)depth, image, trans, K, (float4*)out);
}

// round 13
// speedup vs baseline: 1.2731x; 1.0269x over previous
#include <cuda_runtime.h>
#include <math.h>

#define WG 640      // grid "w" dimension (output dim 2)
#define HG 480      // grid "h" dimension (output dim 3, innermost)
#define IMW 640     // image width
#define IMH 480     // image height
#define MAXB 64
#define HQ (HG / 4)          // float4 groups along h (120)
#define QPB (WG * HQ)        // float4 groups per batch (76800)
#define NPB1 75              // pass1 blocks per batch (75 * 1024 == QPB)
#define THREADS 256

__device__ float g_part[NPB1 * MAXB];     // per-block partials (all overwritten each launch)
__device__ unsigned int g_ctr = 0;        // wrapping counter: returns to 0 every launch
__device__ float g_final;                 // overwritten by pass1's last block each launch

// ---------------------------------------------------------------------------
// Per-batch fold: M = K^-1 @ T[0:3,0:3] @ K (row-vector), C = T[3,0:3] @ K.
// ---------------------------------------------------------------------------
__device__ __forceinline__ void compute_fold(const float* __restrict__ T,
                                             const float* __restrict__ K,
                                             int b, float* sM, float* sC) {
    float a = K[0], bb = K[1], c = K[2];
    float d = K[3], e = K[4], f = K[5];
    float g = K[6], h = K[7], i = K[8];
    float det = a * (e * i - f * h) - bb * (d * i - f * g) + c * (d * h - e * g);
    float inv = 1.0f / det;
    float Ki[9];
    Ki[0] = (e * i - f * h) * inv; Ki[1] = (c * h - bb * i) * inv; Ki[2] = (bb * f - c * e) * inv;
    Ki[3] = (f * g - d * i) * inv; Ki[4] = (a * i - c * g) * inv;  Ki[5] = (c * d - a * f) * inv;
    Ki[6] = (d * h - e * g) * inv; Ki[7] = (bb * g - a * h) * inv; Ki[8] = (a * e - bb * d) * inv;

    const float* Tb = T + b * 16;
    float A[9];
    #pragma unroll
    for (int r = 0; r < 3; r++)
        #pragma unroll
        for (int cc = 0; cc < 3; cc++)
            A[r * 3 + cc] = Ki[r * 3 + 0] * Tb[0 * 4 + cc]
                          + Ki[r * 3 + 1] * Tb[1 * 4 + cc]
                          + Ki[r * 3 + 2] * Tb[2 * 4 + cc];
    #pragma unroll
    for (int r = 0; r < 3; r++)
        #pragma unroll
        for (int cc = 0; cc < 3; cc++)
            sM[r * 3 + cc] = A[r * 3 + 0] * K[0 * 3 + cc]
                           + A[r * 3 + 1] * K[1 * 3 + cc]
                           + A[r * 3 + 2] * K[2 * 3 + cc];
    #pragma unroll
    for (int cc = 0; cc < 3; cc++)
        sC[cc] = Tb[12] * K[cc] + Tb[13] * K[3 + cc] + Tb[14] * K[6 + cc];
}

// ---------------------------------------------------------------------------
// Pass 1: block covers a contiguous 1024-float4 region of one batch; each
// thread issues 4 independent float4 loads up-front (MLP=4). Per-block max
// -> g_part; last block (wrapping atomicInc) reduces partials -> g_final.
// ---------------------------------------------------------------------------
__global__ void stn_max(const float4* __restrict__ depth4,
                        const float* __restrict__ T,
                        const float* __restrict__ K, int npart) {
    __shared__ float sM[9], sC[3];
    int b = blockIdx.y;
    if (threadIdx.x == 0) compute_fold(T, K, b, sM, sC);
    __syncthreads();

    const float4* dep4 = depth4 + (size_t)b * QPB;
    int base = blockIdx.x * 1024 + threadIdx.x;   // 75*1024 == QPB, no bounds check

    // issue all 4 loads before any math (MLP=4)
    float4 dv[4];
    #pragma unroll
    for (int j = 0; j < 4; j++) dv[j] = dep4[base + j * 256];

    float m = -INFINITY;
    #pragma unroll
    for (int j = 0; j < 4; j++) {
        int q = base + j * 256;
        int hq = q % HQ;
        int w  = q / HQ;
        float fh = (float)(hq * 4), fw = (float)w;
        float t0 = fh * sM[0] + fw * sM[3] + sM[6];
        float t1 = fh * sM[1] + fw * sM[4] + sM[7];
        float t2 = fh * sM[2] + fw * sM[5] + sM[8];
        float dep[4] = {dv[j].x, dv[j].y, dv[j].z, dv[j].w};
        #pragma unroll
        for (int i = 0; i < 4; i++) {
            float d0 = dep[i] * t0 + sC[0];
            float d1 = dep[i] * t1 + sC[1];
            float d2 = dep[i] * t2 + sC[2];
            float r = __fdividef(1.0f, d2 + 1e-4f);
            m = fmaxf(m, fmaxf(d0 * r, d1 * r));
            t0 += sM[0]; t1 += sM[1]; t2 += sM[2];
        }
    }

    // block reduce
    #pragma unroll
    for (int off = 16; off > 0; off >>= 1)
        m = fmaxf(m, __shfl_xor_sync(0xFFFFFFFF, m, off));
    __shared__ float sm[THREADS / 32];
    __shared__ bool is_last;
    int lane = threadIdx.x & 31, wid = threadIdx.x >> 5;
    if (lane == 0) sm[wid] = m;
    __syncthreads();
    if (threadIdx.x == 0) {
        float bm = sm[0];
        #pragma unroll
        for (int i = 1; i < THREADS / 32; i++) bm = fmaxf(bm, sm[i]);
        g_part[b * NPB1 + blockIdx.x] = bm;
        __threadfence();
        // wrapping counter: exactly npart increments per launch -> ends at 0,
        // replay-deterministic with no reset kernel.
        unsigned int old = atomicInc(&g_ctr, (unsigned int)(npart - 1));
        is_last = (old == (unsigned int)(npart - 1));
    }
    __syncthreads();
    if (is_last) {
        float mm = -INFINITY;
        for (int i = threadIdx.x; i < npart; i += THREADS) mm = fmaxf(mm, g_part[i]);
        #pragma unroll
        for (int off = 16; off > 0; off >>= 1)
            mm = fmaxf(mm, __shfl_xor_sync(0xFFFFFFFF, mm, off));
        if (lane == 0) sm[wid] = mm;
        __syncthreads();
        if (threadIdx.x == 0) {
            float bm = sm[0];
            #pragma unroll
            for (int i = 1; i < THREADS / 32; i++) bm = fmaxf(bm, sm[i]);
            g_final = bm;
        }
    }
}

// ---------------------------------------------------------------------------
// Pass 2: proven body — float4 over h, branchy bilinear, plain stores.
// (unchanged from the 35.7us version)
// ---------------------------------------------------------------------------
__global__ void stn_sample(const float4* __restrict__ depth4,
                           const float* __restrict__ image,
                           const float* __restrict__ T,
                           const float* __restrict__ K,
                           float4* __restrict__ out4) {
    __shared__ float sM[9], sC[3];
    int b = blockIdx.y;
    if (threadIdx.x == 0) compute_fold(T, K, b, sM, sC);
    __syncthreads();

    float Mx = g_final;                     // single L2-hit load
    float cw = __fdividef((float)IMW, Mx);
    float ch = __fdividef((float)IMH, Mx);

    int q = blockIdx.x * THREADS + threadIdx.x;
    if (q >= QPB) return;
    int hq = q % HQ;
    int w  = q / HQ;

    float fh = (float)(hq * 4), fw = (float)w;
    float t0 = fh * sM[0] + fw * sM[3] + sM[6];
    float t1 = fh * sM[1] + fw * sM[4] + sM[7];
    float t2 = fh * sM[2] + fw * sM[5] + sM[8];

    float4 d4 = depth4[(size_t)b * QPB + q];
    float dep[4] = {d4.x, d4.y, d4.z, d4.w};

    const float* img = image + (size_t)b * 3 * IMH * IMW;
    const int chs = IMH * IMW;

    float a0[4], a1[4], a2[4];

    #pragma unroll
    for (int i = 0; i < 4; i++) {
        float d0 = dep[i] * t0 + sC[0];
        float d1 = dep[i] * t1 + sC[1];
        float d2 = dep[i] * t2 + sC[2];
        t0 += sM[0]; t1 += sM[1]; t2 += sM[2];
        float r = __fdividef(1.0f, d2 + 1e-4f);
        float x = d0 * r * cw - 0.5f;
        float y = d1 * r * ch - 0.5f;

        float x0f = floorf(x), y0f = floorf(y);
        float wx = x - x0f, wy = y - y0f;
        int x0 = (int)x0f, y0 = (int)y0f;
        int x1 = x0 + 1, y1 = y0 + 1;

        float w00 = (1.0f - wx) * (1.0f - wy);
        float w01 = wx * (1.0f - wy);
        float w10 = (1.0f - wx) * wy;
        float w11 = wx * wy;

        bool vx0 = (x0 >= 0) && (x0 < IMW);
        bool vx1 = (x1 >= 0) && (x1 < IMW);
        bool vy0 = (y0 >= 0) && (y0 < IMH);
        bool vy1 = (y1 >= 0) && (y1 < IMH);

        float s0 = 0.0f, s1 = 0.0f, s2 = 0.0f;
        if (vy0) {
            int row = y0 * IMW;
            if (vx0) {
                int o = row + x0;
                s0 += w00 * img[o]; s1 += w00 * img[chs + o]; s2 += w00 * img[2 * chs + o];
            }
            if (vx1) {
                int o = row + x1;
                s0 += w01 * img[o]; s1 += w01 * img[chs + o]; s2 += w01 * img[2 * chs + o];
            }
        }
        if (vy1) {
            int row = y1 * IMW;
            if (vx0) {
                int o = row + x0;
                s0 += w10 * img[o]; s1 += w10 * img[chs + o]; s2 += w10 * img[2 * chs + o];
            }
            if (vx1) {
                int o = row + x1;
                s0 += w11 * img[o]; s1 += w11 * img[chs + o]; s2 += w11 * img[2 * chs + o];
            }
        }
        a0[i] = s0; a1[i] = s1; a2[i] = s2;
    }

    // out[b, c, w, h], h innermost; float4 groups along h (write-back stores)
    size_t base = ((size_t)(b * 3) * WG + w) * HQ + hq;  // float4 units
    const size_t ostride = (size_t)WG * HQ;
    out4[base]               = make_float4(a0[0], a0[1], a0[2], a0[3]);
    out4[base + ostride]     = make_float4(a1[0], a1[1], a1[2], a1[3]);
    out4[base + 2 * ostride] = make_float4(a2[0], a2[1], a2[2], a2[3]);
}

extern "C" void kernel_launch(void* const* d_in, const int* in_sizes, int n_in,
                              void* d_out, int out_size) {
    const float* depth = (const float*)d_in[0];   // [B, 640, 480, 1]
    const float* trans = (const float*)d_in[1];   // [B, 4, 4]
    const float* image = (const float*)d_in[2];   // [B, 3, 480, 640]
    const float* K     = (const float*)d_in[3];   // [3, 3]
    float* out = (float*)d_out;                   // [B, 3, 640, 480]

    int B = in_sizes[0] / (WG * HG);
    int npart = NPB1 * B;

    dim3 g1(NPB1, B);   // 75 x B blocks, 1024 float4s per block
    stn_max<<<g1, THREADS>>>((const float4*)depth, trans, K, npart);

    dim3 g2((QPB + THREADS - 1) / THREADS, B);   // 300 x B
    stn_sample<<<g2, THREADS>>>((const float4*)depth, image, trans, K, (float4*)out);
}